// round 1
// baseline (speedup 1.0000x reference)
#include <cuda_runtime.h>
#include <cuda_bf16.h>
#include <math.h>

// Problem constants
#define BATCH   4
#define SEQ     2048
#define HDIM    1024          // model dim (K for projections, N for output proj)
#define NHEADS  16
#define HEADD   64
#define MROWS   (BATCH * SEQ) // 8192

// ---------------- scratch (static device globals; no runtime allocation) ----
__device__ float g_Pq[(size_t)MROWS * HDIM];   // phi(q)
__device__ float g_Pk[(size_t)MROWS * HDIM];   // phi(k)
__device__ float g_V [(size_t)MROWS * HDIM];   // v
__device__ float g_B [(size_t)MROWS * NHEADS]; // sigmoid(beta proj)
__device__ float g_Y [(size_t)MROWS * HDIM];   // scan output

// ---------------- fp32 SGEMM: C[M,N] = A[M,K] @ W[N,K]^T + bias, epilogue ---
// EPI 0: none; EPI 1: phi(x) = x>0 ? x+1 : exp(x)
#define BM 128
#define BN 128
#define BK 16
#define TM 8
#define TN 8

template<int EPI>
__global__ __launch_bounds__(256)
void sgemm_nt(int M, int N, int K,
              const float* __restrict__ A,
              const float* __restrict__ W,
              const float* __restrict__ bias,
              float* __restrict__ C)
{
    __shared__ float As[BK][BM];
    __shared__ float Bs[BK][BN];

    const int tid  = threadIdx.x;
    const int crow = blockIdx.y * BM;
    const int ccol = blockIdx.x * BN;

    const int tRow = tid / (BN / TN);   // 0..15
    const int tCol = tid % (BN / TN);   // 0..15

    // loader mapping: 64 rows per pass, 4 floats (float4) per thread
    const int ldRow = tid >> 2;         // 0..63
    const int ldCol = (tid & 3) * 4;    // 0,4,8,12

    const float* Aptr = A + (size_t)crow * K;
    const float* Wptr = W + (size_t)ccol * K;

    float acc[TM][TN];
#pragma unroll
    for (int i = 0; i < TM; i++)
#pragma unroll
        for (int j = 0; j < TN; j++) acc[i][j] = 0.f;

    float regM[TM], regN[TN];

    for (int k0 = 0; k0 < K; k0 += BK) {
#pragma unroll
        for (int r = 0; r < BM; r += 64) {
            float4 t = *(const float4*)(Aptr + (size_t)(ldRow + r) * K + k0 + ldCol);
            As[ldCol + 0][ldRow + r] = t.x;
            As[ldCol + 1][ldRow + r] = t.y;
            As[ldCol + 2][ldRow + r] = t.z;
            As[ldCol + 3][ldRow + r] = t.w;
        }
#pragma unroll
        for (int r = 0; r < BN; r += 64) {
            float4 t = *(const float4*)(Wptr + (size_t)(ldRow + r) * K + k0 + ldCol);
            Bs[ldCol + 0][ldRow + r] = t.x;
            Bs[ldCol + 1][ldRow + r] = t.y;
            Bs[ldCol + 2][ldRow + r] = t.z;
            Bs[ldCol + 3][ldRow + r] = t.w;
        }
        __syncthreads();

#pragma unroll
        for (int kk = 0; kk < BK; kk++) {
#pragma unroll
            for (int i = 0; i < TM; i++) regM[i] = As[kk][tRow * TM + i];
#pragma unroll
            for (int j = 0; j < TN; j++) regN[j] = Bs[kk][tCol * TN + j];
#pragma unroll
            for (int i = 0; i < TM; i++)
#pragma unroll
                for (int j = 0; j < TN; j++)
                    acc[i][j] = fmaf(regM[i], regN[j], acc[i][j]);
        }
        __syncthreads();
    }

    // epilogue
#pragma unroll
    for (int i = 0; i < TM; i++) {
        const int row = crow + tRow * TM + i;
#pragma unroll
        for (int j = 0; j < TN; j++) {
            const int col = ccol + tCol * TN + j;
            float c = acc[i][j] + bias[col];
            if (EPI == 1) c = (c > 0.f) ? (c + 1.f) : expf(c);
            C[(size_t)row * N + col] = c;
        }
    }
}

// ---------------- beta projection: Bsig[M,16] = sigmoid(A @ Wb^T + bb) ------
// block: 256 threads handles 16 rows; K chunked by 64 through shared memory.
__global__ __launch_bounds__(256)
void beta_kernel(const float* __restrict__ A,
                 const float* __restrict__ Wb,
                 const float* __restrict__ bb,
                 float* __restrict__ Bsig,
                 int M, int K)
{
    __shared__ float Ash[16][65];
    __shared__ float Wsh[16][65];

    const int tid = threadIdx.x;
    const int m0  = blockIdx.x * 16;

    const int ldRow  = tid / 16;        // 0..15
    const int ldCol4 = (tid % 16) * 4;  // 0..60

    const int tm = tid / 16;            // row within block
    const int n  = tid % 16;            // head

    float acc = 0.f;

    for (int k0 = 0; k0 < K; k0 += 64) {
        {
            float4 t = *(const float4*)(A + (size_t)(m0 + ldRow) * K + k0 + ldCol4);
            Ash[ldRow][ldCol4 + 0] = t.x;
            Ash[ldRow][ldCol4 + 1] = t.y;
            Ash[ldRow][ldCol4 + 2] = t.z;
            Ash[ldRow][ldCol4 + 3] = t.w;
        }
        {
            float4 t = *(const float4*)(Wb + (size_t)ldRow * K + k0 + ldCol4);
            Wsh[ldRow][ldCol4 + 0] = t.x;
            Wsh[ldRow][ldCol4 + 1] = t.y;
            Wsh[ldRow][ldCol4 + 2] = t.z;
            Wsh[ldRow][ldCol4 + 3] = t.w;
        }
        __syncthreads();
#pragma unroll
        for (int k = 0; k < 64; k++)
            acc = fmaf(Ash[tm][k], Wsh[n][k], acc);
        __syncthreads();
    }

    acc += bb[n];
    Bsig[(size_t)(m0 + tm) * NHEADS + n] = 1.f / (1.f + expf(-acc));
}

// ---------------- delta-rule diagonal-state scan ----------------------------
// One block per (batch, head): 64 threads, one per state dim.
// s <- s + b*(v - s*pk)*pk ;  y = s*pq   (s starts at 0)
__global__ __launch_bounds__(64)
void scan_kernel(const float* __restrict__ Pq,
                 const float* __restrict__ Pk,
                 const float* __restrict__ Vb,
                 const float* __restrict__ Bsig,
                 float* __restrict__ Y)
{
    const int bh = blockIdx.x;
    const int b  = bh >> 4;
    const int h  = bh & 15;
    const int d  = threadIdx.x;

    const size_t base = (size_t)b * SEQ * HDIM + (size_t)h * HEADD + d;
    const float* pk = Pk   + base;
    const float* pq = Pq   + base;
    const float* vv = Vb   + base;
    float*       y  = Y    + base;
    const float* bp = Bsig + (size_t)b * SEQ * NHEADS + h;

    float s = 0.f;

    // software-pipelined: prefetch t+1 while computing t
    float cpk = pk[0], cpq = pq[0], cv = vv[0], cb = bp[0];

#pragma unroll 4
    for (int t = 0; t < SEQ; t++) {
        float npk = 0.f, npq = 0.f, nv = 0.f, nb = 0.f;
        if (t + 1 < SEQ) {
            const size_t o = (size_t)(t + 1) * HDIM;
            npk = pk[o]; npq = pq[o]; nv = vv[o];
            nb  = bp[(size_t)(t + 1) * NHEADS];
        }
        // s = s + cb*(cv - s*cpk)*cpk
        s = fmaf(cb * (cv - s * cpk), cpk, s);
        y[(size_t)t * HDIM] = s * cpq;

        cpk = npk; cpq = npq; cv = nv; cb = nb;
    }
}

// ---------------- launch -----------------------------------------------------
extern "C" void kernel_launch(void* const* d_in, const int* in_sizes, int n_in,
                              void* d_out, int out_size)
{
    const float* query = (const float*)d_in[0];
    const float* key   = (const float*)d_in[1];
    const float* value = (const float*)d_in[2];
    const float* beta  = (const float*)d_in[3];
    const float* Wq    = (const float*)d_in[4];
    const float* bq    = (const float*)d_in[5];
    const float* Wk    = (const float*)d_in[6];
    const float* bk    = (const float*)d_in[7];
    const float* Wv    = (const float*)d_in[8];
    const float* bv    = (const float*)d_in[9];
    const float* Wb    = (const float*)d_in[10];
    const float* bb    = (const float*)d_in[11];
    const float* Wo    = (const float*)d_in[12];
    const float* bo    = (const float*)d_in[13];
    float* out = (float*)d_out;

    float *pPq, *pPk, *pV, *pB, *pY;
    cudaGetSymbolAddress((void**)&pPq, g_Pq);
    cudaGetSymbolAddress((void**)&pPk, g_Pk);
    cudaGetSymbolAddress((void**)&pV,  g_V);
    cudaGetSymbolAddress((void**)&pB,  g_B);
    cudaGetSymbolAddress((void**)&pY,  g_Y);

    dim3 grid(HDIM / BN, MROWS / BM);   // (8, 64)
    dim3 block(256);

    // q, k projections with fused phi
    sgemm_nt<1><<<grid, block>>>(MROWS, HDIM, HDIM, query, Wq, bq, pPq);
    sgemm_nt<1><<<grid, block>>>(MROWS, HDIM, HDIM, key,   Wk, bk, pPk);
    // v projection
    sgemm_nt<0><<<grid, block>>>(MROWS, HDIM, HDIM, value, Wv, bv, pV);
    // beta projection + sigmoid
    beta_kernel<<<MROWS / 16, 256>>>(beta, Wb, bb, pB, MROWS, HDIM);
    // diagonal delta-rule scan
    scan_kernel<<<BATCH * NHEADS, 64>>>(pPq, pPk, pV, pB, pY);
    // output projection
    sgemm_nt<0><<<grid, block>>>(MROWS, HDIM, HDIM, pY, Wo, bo, out);
}